// round 7
// baseline (speedup 1.0000x reference)
#include <cuda_runtime.h>
#include <math.h>

#define NX 64
#define NUN 256
#define NY 32
#define NZ 384        // 2*NX + NUN
#define BATCH 32768
#define NSTATE 384    // 128 (z = x||u) + 256 (w)
#define EPB 128       // batch elements per block
#define TB 256        // threads per block = 8 warps; warp owns 16 elems
#define SSTRIDE 130   // state row stride (floats), conflict-free for q-split

typedef unsigned long long ULL;

// ---------------- f32x2 / misc helpers ----------------------------------
__device__ __forceinline__ ULL ffma2(ULL a, ULL b, ULL c) {
    ULL d; asm("fma.rn.f32x2 %0, %1, %2, %3;" : "=l"(d) : "l"(a), "l"(b), "l"(c)); return d;
}
__device__ __forceinline__ ULL fadd2(ULL a, ULL b) {
    ULL d; asm("add.rn.f32x2 %0, %1, %2;" : "=l"(d) : "l"(a), "l"(b)); return d;
}
__device__ __forceinline__ ULL pack2(float lo, float hi) {
    ULL d; asm("mov.b64 %0, {%1,%2};" : "=l"(d) : "f"(lo), "f"(hi)); return d;
}
__device__ __forceinline__ void unpack2(ULL v, float& lo, float& hi) {
    asm("mov.b64 {%0,%1}, %2;" : "=f"(lo), "=f"(hi) : "l"(v));
}
__device__ __forceinline__ ULL shfl_xor64(ULL v, int m) {
    return __shfl_xor_sync(0xFFFFFFFFu, v, m, 32);
}
__device__ __forceinline__ float tanh_fast(float x) {
    float y; asm("tanh.approx.f32 %0, %1;" : "=f"(y) : "f"(x)); return y;
}

// ---------------- device scratch (no cudaMalloc allowed) ----------------
__device__ __align__(16) float g_lT1[NZ * 64];
__device__ __align__(16) float g_lT2[NZ * 32];
__device__ __align__(16) float g_M1[NZ * 64];
__device__ __align__(16) float g_M2[NZ * 32];
__device__ __align__(16) float g_H[256 * 320];      // H[64+r][c], c in [0,320)
// per-chunk staged block (3152 floats):
//   [0,3072)    coef packed unit-pairs: [(kp*384+t)*2 + slot]
//   [3072,3136) diag dg[k*8+j]
//   [3136,3144) bias (b_w/lam)
//   [3144,3152) pad
__device__ __align__(16) float g_CHUNK[32 * 3152];
// y-weights packed m-pairs: rows 0..63 = C2T, 64..319 = D21T
__device__ __align__(16) float g_YWP[320 * 32];

// ---------------- setup kernels (batch-independent weights) --------------

__global__ void k_build_lT(const float* __restrict__ B2, const float* __restrict__ C2,
                           const float* __restrict__ D12, const float* __restrict__ D21,
                           const float* __restrict__ St) {
    int r = blockIdx.x;      // 0..383
    int k = threadIdx.x;     // 0..63
    float v1;
    if (r < 64) {
        float s = 0.f;
        for (int m = 0; m < 32; m++) s += St[k * 32 + m] * C2[m * 64 + r];
        v1 = s;
    } else if (r < 320) {
        int rr = r - 64;
        float s = 0.f;
        for (int m = 0; m < 32; m++) s += St[k * 32 + m] * D21[m * 256 + rr];
        v1 = s - D12[rr * 64 + k];
    } else {
        v1 = B2[(r - 320) * 64 + k];
    }
    g_lT1[r * 64 + k] = v1;
    if (k < 32) {
        float v2;
        if (r < 64)        v2 = C2[k * 64 + r];
        else if (r < 320)  v2 = D21[k * 256 + (r - 64)];
        else               v2 = 0.f;
        g_lT2[r * 32 + k] = v2;
    }
}

__global__ void k_build_M(const float* __restrict__ Rinv, const float* __restrict__ Q) {
    int r = blockIdx.x, k = threadIdx.x;
    float s = 0.f;
    for (int t = 0; t < 64; t++) s += g_lT1[r * 64 + t] * Rinv[t * 64 + k];
    g_M1[r * 64 + k] = s;
    if (k < 32) {
        float s2 = 0.f;
        for (int t = 0; t < 32; t++) s2 += g_lT2[r * 32 + t] * Q[t * 32 + k];
        g_M2[r * 32 + k] = s2;
    }
}

__global__ void k_build_H(const float* __restrict__ X) {
    int idx = blockIdx.x * blockDim.x + threadIdx.x;
    if (idx >= 256 * 320) return;
    int r = idx / 320, c = idx % 320;
    int a = 64 + r;
    float h = 0.f;
    for (int t = 0; t < NZ; t++) h += X[t * NZ + a] * X[t * NZ + c];
    if (c == a) h += 0.001f;
    float h1 = 0.f;
    for (int k = 0; k < 64; k++) h1 += g_M1[a * 64 + k] * g_lT1[c * 64 + k];
    float h2 = 0.f;
    for (int k = 0; k < 32; k++) h2 += g_M2[a * 32 + k] * g_lT2[c * 32 + k];
    g_H[idx] = h + h1 - h2;
}

// grid 320: i<64 -> C2T rows of g_YWP; else unit uu -> g_CHUNK slices + D21T
__global__ void k_finalize(const float* __restrict__ D12, const float* __restrict__ D21,
                           const float* __restrict__ C2, const float* __restrict__ b) {
    int i = blockIdx.x;
    int tx = threadIdx.x;
    if (i < 64) {
        if (tx < 32) g_YWP[i * 32 + tx] = C2[tx * 64 + i];
        return;
    }
    int uu = i - 64;  // 0..255
    __shared__ float s_inv;
    if (tx == 0) {
        float lam = 0.5f * g_H[uu * 320 + 64 + uu];
        s_inv = 1.f / lam;
    }
    __syncthreads();
    float inv = s_inv;
    int c = uu >> 3, k = uu & 7, kp = k >> 1, slot = k & 1;
    float* chunk = g_CHUNK + (size_t)c * 3152;
    for (int t = tx; t < NSTATE; t += blockDim.x) {
        float val;
        if (t < 64) {
            val = -g_H[uu * 320 + t] * inv;                 // C_1 / lam
        } else if (t < 128) {
            val = D12[uu * 64 + (t - 64)] * inv;            // D_12 / lam
        } else {
            int j = t - 128;
            val = (uu >= 1 && j <= uu - 2) ? (-g_H[(uu - 1) * 320 + 64 + j]) * inv : 0.f;
        }
        chunk[(kp * 384 + t) * 2 + slot] = val;
    }
    if (tx < 8) {
        int j = c * 8 + tx;   // within-chunk column
        float val = (uu >= 1 && j <= uu - 2) ? (-g_H[(uu - 1) * 320 + 64 + j]) * inv : 0.f;
        chunk[3072 + k * 8 + tx] = val;
    }
    if (tx == 0) chunk[3136 + k] = b[64 + uu] * inv;
    if (tx < 32) g_YWP[(64 + uu) * 32 + tx] = D21[tx * 256 + uu];
}

// ---------------- main kernel ---------------------------------------------
// 128 elems/block, 256 threads = 8 warps. Each warp owns 16 elems:
// lane = (q<<4) | e_local, q in {0,1} splits p-blocks by parity.
// Per chunk: p-loop (per-lane p), shfl_xor(16) reduce, diag+tanh redundant
// on both q-groups, q==0 stores w. Coefficients double-buffered in shared,
// LDG at chunk top -> STS at chunk end -> ONE block barrier per chunk.
//
// Shared layout (ULL units):
#define SM_STATE 0                        // float[384][130]  = 24960 ULL
#define SM_CH0   24960                    // 1576 ULL (3152 floats)
#define SM_CH1   (SM_CH0 + 1576)          // 26536
#define SM_BY    (SM_CH1 + 1576)          // 28112, 32 floats = 16 ULL
#define SM_TOTAL (SM_BY + 16)             // 28128 ULL = 225024 B

__global__ void __launch_bounds__(TB, 1)
k_main(const float* __restrict__ u, const float* __restrict__ x0,
       const float* __restrict__ b, float* __restrict__ out) {
    extern __shared__ ULL sh[];
    float* s_state = (float*)sh;
    float* s_by    = (float*)(sh + SM_BY);

    const int tid  = threadIdx.x;
    const int lane = tid & 31;
    const int warp = tid >> 5;
    const int elem = (warp << 4) | (lane & 15);   // 0..127
    const int q    = lane >> 4;                   // p-parity group
    const int b0   = blockIdx.x * EPB;

    if (tid < 32) s_by[tid] = b[320 + tid];

    // ---- load z = [x(64) | u(64)] (row-transposed, conflict-free) ----
    {
        const int e = tid & 127;
        const float4* src = (const float4*)(((tid >> 7) ? u : x0) + (size_t)(b0 + e) * 64);
        const int rbase = (tid >> 7) * 64;
#pragma unroll
        for (int q4 = 0; q4 < 16; q4++) {
            float4 v = src[q4];
            s_state[(rbase + q4 * 4 + 0) * SSTRIDE + e] = v.x;
            s_state[(rbase + q4 * 4 + 1) * SSTRIDE + e] = v.y;
            s_state[(rbase + q4 * 4 + 2) * SSTRIDE + e] = v.z;
            s_state[(rbase + q4 * 4 + 3) * SSTRIDE + e] = v.w;
        }
    }
    // ---- stage chunk 0 into CH0 ----
    {
        const float4* src = (const float4*)g_CHUNK;
        float4* dst = (float4*)(sh + SM_CH0);
#pragma unroll
        for (int i = 0; i < 4; i++) { int idx = i * TB + tid; if (idx < 788) dst[idx] = src[idx]; }
    }
    __syncthreads();

    // ================= main chunk loop =================
    for (int c = 0; c < 32; c++) {
        const ULL* buf = sh + ((c & 1) ? SM_CH1 : SM_CH0);

        // prefetch chunk c+1 from global (hidden under p-loop)
        float4 pf[4];
        if (c < 31) {
            const float4* src = (const float4*)(g_CHUNK + (size_t)(c + 1) * 3152);
#pragma unroll
            for (int i = 0; i < 4; i++) { int idx = i * TB + tid; if (idx < 788) pf[i] = src[idx]; }
        }

        // ---- p-loop: per-lane p = q, q+2, ... ----
        ULL acc[4];
#pragma unroll
        for (int kp = 0; kp < 4; kp++) acc[kp] = 0ull;
        const int P = 16 + c;
        for (int p = q; p < P; p += 2) {
            ULL svd[8];
#pragma unroll
            for (int j = 0; j < 8; j++) {
                float v = s_state[(p * 8 + j) * SSTRIDE + elem];
                svd[j] = pack2(v, v);
            }
#pragma unroll
            for (int kp = 0; kp < 4; kp++) {
                const ulonglong2* cf = (const ulonglong2*)(buf + kp * NSTATE + p * 8);
                ulonglong2 c0 = cf[0], c1 = cf[1], c2v = cf[2], c3 = cf[3];
                acc[kp] = ffma2(svd[0], c0.x, acc[kp]);
                acc[kp] = ffma2(svd[1], c0.y, acc[kp]);
                acc[kp] = ffma2(svd[2], c1.x, acc[kp]);
                acc[kp] = ffma2(svd[3], c1.y, acc[kp]);
                acc[kp] = ffma2(svd[4], c2v.x, acc[kp]);
                acc[kp] = ffma2(svd[5], c2v.y, acc[kp]);
                acc[kp] = ffma2(svd[6], c3.x, acc[kp]);
                acc[kp] = ffma2(svd[7], c3.y, acc[kp]);
            }
        }
        // ---- cross-parity reduce: one shfl round ----
#pragma unroll
        for (int kp = 0; kp < 4; kp++) acc[kp] = fadd2(acc[kp], shfl_xor64(acc[kp], 16));

        // ---- serial 8x8 diag + tanh (redundant on both q groups) ----
        {
            float a[8];
#pragma unroll
            for (int kp = 0; kp < 4; kp++) unpack2(acc[kp], a[2 * kp], a[2 * kp + 1]);
            const float* dgf = (const float*)buf + 3072;
            const float* bsf = (const float*)buf + 3136;
            float wl[8];
#pragma unroll
            for (int k = 0; k < 8; k++) {
                float s = a[k] + bsf[k];
#pragma unroll
                for (int j = 0; j < 8; j++)
                    if (j < k) s += wl[j] * dgf[k * 8 + j];
                wl[k] = tanh_fast(s);
            }
            if (q == 0) {
#pragma unroll
                for (int k = 0; k < 8; k++)
                    s_state[(128 + c * 8 + k) * SSTRIDE + elem] = wl[k];
            }
        }

        // ---- commit staged chunk c+1, single barrier ----
        if (c < 31) {
            float4* dst = (float4*)(sh + ((c & 1) ? SM_CH0 : SM_CH1));
#pragma unroll
            for (int i = 0; i < 4; i++) { int idx = i * TB + tid; if (idx < 788) dst[idx] = pf[i]; }
        }
        __syncthreads();   // coef(c+1) visible; w(c) visible to all warps
    }

    // ================= tail: y = x@C2T + w@D21T =================
    ULL yacc[16];
#pragma unroll
    for (int m = 0; m < 16; m++) yacc[m] = 0ull;
    const int e    = tid & 127;
    const int half = tid >> 7;

    for (int r = 0; r < 5; r++) {
        __syncthreads();   // protect staging region
        {
            const float4* src = (const float4*)g_YWP + r * 512;  // 64 rows x 32 floats
            float4* dst = (float4*)(sh + SM_CH0);
            dst[tid] = src[tid];
            dst[TB + tid] = src[TB + tid];
        }
        __syncthreads();
        const int srow = (r == 0) ? 0 : 128 + (r - 1) * 64;
#pragma unroll 2
        for (int jj = 0; jj < 32; jj++) {
            int lrow = half * 32 + jj;
            float v = s_state[(srow + lrow) * SSTRIDE + e];
            ULL vd = pack2(v, v);
            const ulonglong2* cf = (const ulonglong2*)(sh + SM_CH0) + lrow * 8;
#pragma unroll
            for (int mm = 0; mm < 8; mm++) {
                ulonglong2 cv = cf[mm];
                yacc[2 * mm]     = ffma2(vd, cv.x, yacc[2 * mm]);
                yacc[2 * mm + 1] = ffma2(vd, cv.y, yacc[2 * mm + 1]);
            }
        }
    }

    __syncthreads();
    if (half) {
#pragma unroll
        for (int m = 0; m < 16; m++) sh[e * 17 + m] = yacc[m];   // padded, conflict-free
    }
    __syncthreads();
    if (!half) {
        float* s_out = (float*)(sh + 2176);   // 128*33 floats
#pragma unroll
        for (int m = 0; m < 16; m++) {
            ULL t = fadd2(yacc[m], sh[e * 17 + m]);
            float lo, hi; unpack2(t, lo, hi);
            s_out[e * 33 + 2 * m]     = lo + s_by[2 * m];
            s_out[e * 33 + 2 * m + 1] = hi + s_by[2 * m + 1];
        }
    }
    __syncthreads();
    {
        const float* s_out = (const float*)(sh + 2176);
        for (int idx = tid; idx < EPB * 32; idx += TB) {
            int ee = idx >> 5, m = idx & 31;
            out[(b0 + ee) * 32 + m] = s_out[ee * 33 + m];
        }
    }
}

// ---------------- launch ----------------

extern "C" void kernel_launch(void* const* d_in, const int* in_sizes, int n_in,
                              void* d_out, int out_size) {
    const float* u    = (const float*)d_in[0];
    const float* x0   = (const float*)d_in[1];
    const float* B2   = (const float*)d_in[2];
    const float* C2   = (const float*)d_in[3];
    const float* D12  = (const float*)d_in[4];
    const float* D21  = (const float*)d_in[5];
    const float* b    = (const float*)d_in[6];
    const float* X    = (const float*)d_in[7];
    // d_in[8] = Y1 (unused by reference)
    const float* St   = (const float*)d_in[9];
    const float* Q    = (const float*)d_in[10];
    const float* Rinv = (const float*)d_in[11];
    float* out = (float*)d_out;

    k_build_lT<<<NZ, 64>>>(B2, C2, D12, D21, St);
    k_build_M<<<NZ, 64>>>(Rinv, Q);
    k_build_H<<<(256 * 320) / 128, 128>>>(X);
    k_finalize<<<320, 128>>>(D12, D21, C2, b);

    const size_t shbytes = (size_t)SM_TOTAL * sizeof(ULL);   // 225024 B
    cudaFuncSetAttribute(k_main, cudaFuncAttributeMaxDynamicSharedMemorySize, (int)shbytes);
    k_main<<<BATCH / EPB, TB, shbytes>>>(u, x0, b, out);
}